// round 2
// baseline (speedup 1.0000x reference)
#include <cuda_runtime.h>

// Problem constants (fixed shapes for this dataset)
#define Nn 50000
#define Ff 256
#define Oo 256
#define Rr 3
#define Ee 1600000
#define NB (Rr*Nn)     // 150000 (r,row) buckets
#define TE (Rr*Ee)     // 4.8M edges total

// -------- scratch (static __device__ globals; allocation-free) --------
__device__ float g_h[(size_t)Rr*Nn*Oo];     // 153.6 MB: h_r = x @ W_r
__device__ float g_agg[(size_t)Nn*Oo];      // 51.2 MB: sum_r A_r h_r
__device__ float g_Wfull[512*256];          // [Wcomb(0:256) ; Bcomb(256:512)]
__device__ int   g_row_start[NB+1];
__device__ int   g_cursor[NB];
__device__ int   g_bsums[256];
__device__ int   g_ecol[TE];
__device__ float g_eval[TE];

// -------- weight prep: Wcomb = W2lo + W2hi ; Bcomb = B[2] @ W2hi --------
__global__ void prep_weights(const float* __restrict__ B, const float* __restrict__ W2)
{
    const float* B2  = B  + 2*Ff*Oo;        // B[-1]
    const float* W2l = W2 + 2*2*Oo*Oo;      // W2[-1], shape [512,256]
    int f = blockIdx.x;     // 0..255
    int o = threadIdx.x;    // 0..255
    g_Wfull[f*Oo + o] = W2l[f*Oo + o] + W2l[(Oo+f)*Oo + o];
    float acc = 0.f;
    #pragma unroll 8
    for (int k = 0; k < Oo; k++)
        acc += B2[f*Oo + k] * W2l[(Oo+k)*Oo + o];
    g_Wfull[(Oo+f)*Oo + o] = acc;
}

// -------- SGEMM: C = A @ B, A split across two sources at k=splitK ------
// A0/A1 row stride fixed 256. B row stride fixed 256. C row stride fixed 256.
__global__ __launch_bounds__(256)
void sgemm128(const float* __restrict__ A0, const float* __restrict__ A1,
              const float* __restrict__ Bm, float* __restrict__ C,
              int M, int K, int splitK, long Bz, long Cz, int relu)
{
    __shared__ float As[16][128];
    __shared__ float Bs[16][128];
    const int m0 = blockIdx.x * 128;
    const int n0 = blockIdx.y * 128;
    const float* Bbase = Bm + (long)blockIdx.z * Bz;
    float*       Cbase = C  + (long)blockIdx.z * Cz;
    const int tid = threadIdx.x;
    const int tx  = tid & 15;
    const int ty  = tid >> 4;

    float acc[8][8];
    #pragma unroll
    for (int i = 0; i < 8; i++)
        #pragma unroll
        for (int j = 0; j < 8; j++) acc[i][j] = 0.f;

    for (int k0 = 0; k0 < K; k0 += 16) {
        const float* Ap = (k0 < splitK) ? (A0 + k0) : (A1 + (k0 - splitK));
        // A tile 128x16, transposed into As[k][m]
        #pragma unroll
        for (int q0 = 0; q0 < 2; q0++) {
            int q   = tid*2 + q0;          // 0..511 float4s
            int row = q >> 2;              // 0..127
            int kk  = (q & 3) * 4;         // 0,4,8,12
            float4 v = make_float4(0.f,0.f,0.f,0.f);
            if (m0 + row < M)
                v = *(const float4*)(Ap + (size_t)(m0 + row)*256 + kk);
            As[kk+0][row] = v.x; As[kk+1][row] = v.y;
            As[kk+2][row] = v.z; As[kk+3][row] = v.w;
        }
        // B tile 16x128
        #pragma unroll
        for (int q0 = 0; q0 < 2; q0++) {
            int q   = tid*2 + q0;
            int kr  = q >> 5;              // 0..15
            int col = (q & 31) * 4;        // 0..124
            float4 v = *(const float4*)(Bbase + (size_t)(k0 + kr)*256 + n0 + col);
            *(float4*)&Bs[kr][col] = v;
        }
        __syncthreads();
        #pragma unroll
        for (int kk = 0; kk < 16; kk++) {
            float a[8], b[8];
            *(float4*)&a[0] = *(const float4*)&As[kk][ty*8];
            *(float4*)&a[4] = *(const float4*)&As[kk][ty*8 + 4];
            *(float4*)&b[0] = *(const float4*)&Bs[kk][tx*8];
            *(float4*)&b[4] = *(const float4*)&Bs[kk][tx*8 + 4];
            #pragma unroll
            for (int i = 0; i < 8; i++)
                #pragma unroll
                for (int j = 0; j < 8; j++)
                    acc[i][j] += a[i] * b[j];
        }
        __syncthreads();
    }

    #pragma unroll
    for (int i = 0; i < 8; i++) {
        int m = m0 + ty*8 + i;
        if (m < M) {
            #pragma unroll
            for (int j = 0; j < 8; j += 4) {
                float4 v = make_float4(acc[i][j], acc[i][j+1], acc[i][j+2], acc[i][j+3]);
                if (relu) {
                    v.x = fmaxf(v.x, 0.f); v.y = fmaxf(v.y, 0.f);
                    v.z = fmaxf(v.z, 0.f); v.w = fmaxf(v.w, 0.f);
                }
                *(float4*)(Cbase + (size_t)m*256 + n0 + tx*8 + j) = v;
            }
        }
    }
}

// -------- CSR build --------
__global__ void zero_counts()
{
    int i = blockIdx.x*256 + threadIdx.x;
    if (i < NB) g_cursor[i] = 0;
}

__global__ void count_edges(const int* __restrict__ rows, int E)
{
    int idx = blockIdx.x*256 + threadIdx.x;
    if (idx < 3*E) {
        int r = idx / E;
        atomicAdd(&g_cursor[r*Nn + rows[idx]], 1);
    }
}

__global__ void scan_a(int n)
{
    __shared__ int sh[1024];
    int i = blockIdx.x*1024 + threadIdx.x;
    int v = (i < n) ? g_cursor[i] : 0;
    sh[threadIdx.x] = v;
    __syncthreads();
    for (int off = 1; off < 1024; off <<= 1) {
        int t = (threadIdx.x >= off) ? sh[threadIdx.x - off] : 0;
        __syncthreads();
        sh[threadIdx.x] += t;
        __syncthreads();
    }
    if (i < n) g_row_start[i] = sh[threadIdx.x] - v;   // exclusive
    if (threadIdx.x == 1023) g_bsums[blockIdx.x] = sh[1023];
}

__global__ void scan_b(int nb)
{
    __shared__ int sh[256];
    int v = (threadIdx.x < nb) ? g_bsums[threadIdx.x] : 0;
    sh[threadIdx.x] = v;
    __syncthreads();
    for (int off = 1; off < 256; off <<= 1) {
        int t = (threadIdx.x >= off) ? sh[threadIdx.x - off] : 0;
        __syncthreads();
        sh[threadIdx.x] += t;
        __syncthreads();
    }
    if (threadIdx.x < nb) g_bsums[threadIdx.x] = sh[threadIdx.x] - v;  // exclusive
}

__global__ void scan_c(int n, int total)
{
    int i = blockIdx.x*1024 + threadIdx.x;
    if (i < n) {
        int val = g_row_start[i] + g_bsums[blockIdx.x];
        g_row_start[i] = val;
        g_cursor[i]    = val;   // cursor for the scatter pass
    }
    if (i == 0) g_row_start[n] = total;
}

__global__ void scatter_edges(const int* __restrict__ rows,
                              const int* __restrict__ cols,
                              const float* __restrict__ vals, int E)
{
    int idx = blockIdx.x*256 + threadIdx.x;
    if (idx < 3*E) {
        int r = idx / E;
        int pos = atomicAdd(&g_cursor[r*Nn + rows[idx]], 1);
        g_ecol[pos] = cols[idx];
        g_eval[pos] = vals[idx];
    }
}

// -------- row-parallel SpMM: agg[n][:] (+)= sum_{e in bucket(r,n)} val*h_r[col][:]
__global__ __launch_bounds__(256)
void spmm_rel(int r, int init)
{
    __shared__ int   scol[256];
    __shared__ float sval[256];
    const int n = blockIdx.x;
    const int o = threadIdx.x;
    const float* hr = g_h + (size_t)r*Nn*Oo;
    const int s = g_row_start[r*Nn + n];
    const int e = g_row_start[r*Nn + n + 1];

    float acc = init ? 0.f : g_agg[(size_t)n*Oo + o];
    for (int base = s; base < e; base += 256) {
        int cnt = min(256, e - base);
        __syncthreads();
        if (o < cnt) { scol[o] = g_ecol[base + o]; sval[o] = g_eval[base + o]; }
        __syncthreads();
        #pragma unroll 4
        for (int j = 0; j < cnt; j++)
            acc += sval[j] * hr[(size_t)scol[j]*Oo + o];
    }
    g_agg[(size_t)n*Oo + o] = acc;
}

// -------- launcher --------
extern "C" void kernel_launch(void* const* d_in, const int* in_sizes, int n_in,
                              void* d_out, int out_size)
{
    const float* x    = (const float*)d_in[0];
    const int*   erow = (const int*)  d_in[1];
    const int*   ecol = (const int*)  d_in[2];
    const float* eval = (const float*)d_in[3];
    const float* W    = (const float*)d_in[4];
    const float* B    = (const float*)d_in[5];
    const float* W2   = (const float*)d_in[6];
    float* out = (float*)d_out;

    const int E = in_sizes[1] / 3;
    const int M = Nn;

    float *hptr, *aggptr, *wfull;
    cudaGetSymbolAddress((void**)&hptr,   g_h);
    cudaGetSymbolAddress((void**)&aggptr, g_agg);
    cudaGetSymbolAddress((void**)&wfull,  g_Wfull);

    // weights prep (tiny)
    prep_weights<<<256, 256>>>(B, W2);

    // h_r = x @ W_r for all 3 relations in one launch (grid.z = r)
    dim3 gh((M + 127)/128, 2, 3);
    sgemm128<<<gh, 256>>>(x, x, W, hptr, M, 256, 256,
                          (long)Ff*Oo, (long)Nn*Oo, 0);

    // CSR build
    zero_counts  <<<(NB + 255)/256, 256>>>();
    count_edges  <<<(3*E + 255)/256, 256>>>(erow, E);
    scan_a       <<<(NB + 1023)/1024, 1024>>>(NB);
    scan_b       <<<1, 256>>>((NB + 1023)/1024);
    scan_c       <<<(NB + 1023)/1024, 1024>>>(NB, 3*E);
    scatter_edges<<<(3*E + 255)/256, 256>>>(erow, ecol, eval, E);

    // agg = sum_r A_r @ h_r  (one relation per launch keeps h_r L2-resident)
    for (int r = 0; r < 3; r++)
        spmm_rel<<<Nn, 256>>>(r, r == 0);

    // out = relu([agg | x] @ [Wcomb ; Bcomb])
    dim3 gf((M + 127)/128, 2, 1);
    sgemm128<<<gf, 256>>>(aggptr, x, wfull, out, M, 512, 256, 0, 0, 1);
}

// round 4
// speedup vs baseline: 1.0813x; 1.0813x over previous
#include <cuda_runtime.h>
#include <cuda_bf16.h>
#include <cstdint>

// Problem constants (fixed shapes for this dataset)
#define Nn 50000
#define Ff 256
#define Oo 256
#define Rr 3
#define Ee 1600000
#define NB (Rr*Nn)     // 150000 (r,row) buckets
#define TE (Rr*Ee)     // 4.8M edges total
#define KK 1024        // concat-K of the final GEMM

// ================= scratch (static __device__ globals) =================
__device__ unsigned short g_Ahi[(size_t)Nn*KK];   // bf16 hi of [z0|z1|z2|x], 102.4MB
__device__ unsigned short g_Alo[(size_t)Nn*KK];   // bf16 lo
__device__ unsigned short g_Bhi[(size_t)256*KK];  // B^T [n=256][k=1024] bf16 hi
__device__ unsigned short g_Blo[(size_t)256*KK];
__device__ float g_Wcomb[256*256];                // W2lo + W2hi
__device__ int   g_row_start[NB+1];
__device__ int   g_cursor[NB];
__device__ int   g_bsums[256];
__device__ int   g_ecol[TE];
__device__ float g_eval[TE];

// ================= helpers =================
__device__ __forceinline__ uint32_t smem_u32(const void* p) {
    uint32_t a;
    asm("{ .reg .u64 t; cvta.to.shared.u64 t, %1; cvt.u32.u64 %0, t; }" : "=r"(a) : "l"(p));
    return a;
}
__device__ __forceinline__ void ldsm4(uint32_t* r, uint32_t addr) {
    asm volatile("ldmatrix.sync.aligned.m8n8.x4.shared.b16 {%0,%1,%2,%3}, [%4];"
        : "=r"(r[0]), "=r"(r[1]), "=r"(r[2]), "=r"(r[3]) : "r"(addr));
}
__device__ __forceinline__ void ldsm2(uint32_t* r, uint32_t addr) {
    asm volatile("ldmatrix.sync.aligned.m8n8.x2.shared.b16 {%0,%1}, [%2];"
        : "=r"(r[0]), "=r"(r[1]) : "r"(addr));
}
__device__ __forceinline__ void mma16816(float* d, const uint32_t* a, const uint32_t* b) {
    asm volatile("mma.sync.aligned.m16n8k16.row.col.f32.bf16.bf16.f32 "
        "{%0,%1,%2,%3}, {%4,%5,%6,%7}, {%8,%9}, {%0,%1,%2,%3};"
        : "+f"(d[0]), "+f"(d[1]), "+f"(d[2]), "+f"(d[3])
        : "r"(a[0]), "r"(a[1]), "r"(a[2]), "r"(a[3]), "r"(b[0]), "r"(b[1]));
}
__device__ __forceinline__ unsigned short f2bf_bits(float v) {
    __nv_bfloat16 h = __float2bfloat16(v);
    return *reinterpret_cast<unsigned short*>(&h);
}

// ================= weight prep =================
// Wcomb = W2[-1][0:256] + W2[-1][256:512]
__global__ void prep_wcomb(const float* __restrict__ W2)
{
    const float* W2l = W2 + 2*2*Oo*Oo;  // [512,256]
    int f = blockIdx.x, o = threadIdx.x;
    g_Wcomb[f*Oo + o] = W2l[f*Oo + o] + W2l[(Oo+f)*Oo + o];
}
// For z<3: Bcat[z*256+f][o] = (W_z @ Wcomb)[f][o]; z==3: (B2 @ W2hi)[f][o]
// Stored transposed as B^T bf16 hi/lo: g_B*[o*1024 + z*256 + f]
__global__ void prep_bcat(const float* __restrict__ W, const float* __restrict__ B,
                          const float* __restrict__ W2)
{
    int f = blockIdx.x, z = blockIdx.y, o = threadIdx.x;
    const float* W2l = W2 + 2*2*Oo*Oo;
    float acc = 0.f;
    if (z < 3) {
        const float* Wz = W + (size_t)z*Ff*Oo;
        #pragma unroll 8
        for (int k = 0; k < 256; k++)
            acc += Wz[f*Oo + k] * g_Wcomb[k*Oo + o];
    } else {
        const float* B2 = B + 2*Ff*Oo;
        #pragma unroll 8
        for (int k = 0; k < 256; k++)
            acc += B2[f*Oo + k] * W2l[(Oo+k)*Oo + o];
    }
    unsigned short hi = f2bf_bits(acc);
    __nv_bfloat16 hb = *reinterpret_cast<__nv_bfloat16*>(&hi);
    unsigned short lo = f2bf_bits(acc - __bfloat162float(hb));
    size_t idx = (size_t)o*KK + z*256 + f;
    g_Bhi[idx] = hi;
    g_Blo[idx] = lo;
}

// ================= CSR build =================
__global__ void zero_counts()
{
    int i = blockIdx.x*256 + threadIdx.x;
    if (i < NB) g_cursor[i] = 0;
}
__global__ void count_edges(const int* __restrict__ rows, int E)
{
    int idx = blockIdx.x*256 + threadIdx.x;
    if (idx < 3*E) {
        int r = idx / E;
        atomicAdd(&g_cursor[r*Nn + rows[idx]], 1);
    }
}
__global__ void scan_a(int n)
{
    __shared__ int sh[1024];
    int i = blockIdx.x*1024 + threadIdx.x;
    int v = (i < n) ? g_cursor[i] : 0;
    sh[threadIdx.x] = v;
    __syncthreads();
    for (int off = 1; off < 1024; off <<= 1) {
        int t = (threadIdx.x >= off) ? sh[threadIdx.x - off] : 0;
        __syncthreads();
        sh[threadIdx.x] += t;
        __syncthreads();
    }
    if (i < n) g_row_start[i] = sh[threadIdx.x] - v;
    if (threadIdx.x == 1023) g_bsums[blockIdx.x] = sh[1023];
}
__global__ void scan_b(int nb)
{
    __shared__ int sh[256];
    int v = (threadIdx.x < nb) ? g_bsums[threadIdx.x] : 0;
    sh[threadIdx.x] = v;
    __syncthreads();
    for (int off = 1; off < 256; off <<= 1) {
        int t = (threadIdx.x >= off) ? sh[threadIdx.x - off] : 0;
        __syncthreads();
        sh[threadIdx.x] += t;
        __syncthreads();
    }
    if (threadIdx.x < nb) g_bsums[threadIdx.x] = sh[threadIdx.x] - v;
}
__global__ void scan_c(int n, int total)
{
    int i = blockIdx.x*1024 + threadIdx.x;
    if (i < n) {
        int val = g_row_start[i] + g_bsums[blockIdx.x];
        g_row_start[i] = val;
        g_cursor[i]    = val;
    }
    if (i == 0) g_row_start[n] = total;
}
__global__ void scatter_edges(const int* __restrict__ rows,
                              const int* __restrict__ cols,
                              const float* __restrict__ vals, int E)
{
    int idx = blockIdx.x*256 + threadIdx.x;
    if (idx < 3*E) {
        int r = idx / E;
        int pos = atomicAdd(&g_cursor[r*Nn + rows[idx]], 1);
        g_ecol[pos] = cols[idx];
        g_eval[pos] = vals[idx];
    }
}

// ===== SpMM: z_r[n][:] = sum_e val*x[col][:]; write bf16 hi/lo into A-cat =====
__global__ __launch_bounds__(256)
void spmm_all(const float* __restrict__ x)
{
    __shared__ int   scol[256];
    __shared__ float sval[256];
    const int n = blockIdx.x;
    const int r = blockIdx.y;
    const int o = threadIdx.x;
    const int s = g_row_start[r*Nn + n];
    const int e = g_row_start[r*Nn + n + 1];

    float acc = 0.f;
    for (int base = s; base < e; base += 256) {
        int cnt = min(256, e - base);
        __syncthreads();
        if (o < cnt) { scol[o] = g_ecol[base + o]; sval[o] = g_eval[base + o]; }
        __syncthreads();
        #pragma unroll 4
        for (int j = 0; j < cnt; j++)
            acc += sval[j] * x[(size_t)scol[j]*256 + o];
    }
    unsigned short hi = f2bf_bits(acc);
    __nv_bfloat16 hb = *reinterpret_cast<__nv_bfloat16*>(&hi);
    unsigned short lo = f2bf_bits(acc - __bfloat162float(hb));
    size_t idx = (size_t)n*KK + r*256 + o;
    g_Ahi[idx] = hi;
    g_Alo[idx] = lo;
}

// ===== x -> bf16 hi/lo into A-cat cols [768,1024) =====
__global__ void xconv(const float* __restrict__ x)
{
    int idx = blockIdx.x*256 + threadIdx.x;
    if (idx < Nn*256) {
        int n = idx >> 8, f = idx & 255;
        float v = x[idx];
        unsigned short hi = f2bf_bits(v);
        __nv_bfloat16 hb = *reinterpret_cast<__nv_bfloat16*>(&hi);
        unsigned short lo = f2bf_bits(v - __bfloat162float(hb));
        size_t di = (size_t)n*KK + 768 + f;
        g_Ahi[di] = hi;
        g_Alo[di] = lo;
    }
}

// ===== mma.sync GEMM: out = relu(Acat[N,1024] @ Bcat[1024,256]) =====
// 3-term bf16 split: Ahi*Bhi + Ahi*Blo + Alo*Bhi, fp32 accumulators.
// CTA tile 128x256, 512 threads (16 warps as 4x4), warp tile 32x64.
// smem rows padded to 80B -> conflict-free ldmatrix without XOR swizzle.
// Byte offsets inside dynamic smem:
#define BY_AHI 0u
#define BY_ALO 10240u
#define BY_BHI 20480u
#define BY_BLO 40960u
#define SM_BYTES 61440

__global__ __launch_bounds__(512, 1)
void gemm_final(float* __restrict__ out)
{
    extern __shared__ __align__(16) char sm[];
    const uint32_t sbase = smem_u32(sm);
    const int tid  = threadIdx.x;
    const int lane = tid & 31;
    const int wid  = tid >> 5;
    const int m0   = blockIdx.x * 128;
    const int wm   = (wid >> 2) * 32;   // warp row block
    const int wn   = (wid & 3) * 64;    // warp col block

    float acc[2][8][4];
    #pragma unroll
    for (int mi = 0; mi < 2; mi++)
        #pragma unroll
        for (int nj = 0; nj < 8; nj++)
            #pragma unroll
            for (int q = 0; q < 4; q++) acc[mi][nj][q] = 0.f;

    // global load mapping: 512 threads, A tile 128 rows x 4 16B-chunks
    const int arow = tid >> 2, ach = tid & 3;
    const bool mval = (m0 + arow) < Nn;
    const long gA  = (long)(m0 + arow) * 1024 + ach * 8;
    const uint32_t sA_st = (uint32_t)(arow * 80 + ach * 16);
    // B tile 256 rows x 4 chunks -> 2 per thread
    const long gB0 = (long)arow * 1024 + ach * 8;          // rows 0..127
    const long gB1 = (long)(arow + 128) * 1024 + ach * 8;  // rows 128..255
    const uint32_t sB_st0 = (uint32_t)(arow * 80 + ach * 16);
    const uint32_t sB_st1 = (uint32_t)((arow + 128) * 80 + ach * 16);

    // ldmatrix per-thread address components
    const int grp = lane >> 3, r8 = lane & 7;
    // A: row = wm + mi*16 + (grp&1)*8 + r8, chunk = kq*2 + (grp>>1)
    const uint32_t aRowB = (uint32_t)((wm + (grp & 1) * 8 + r8) * 80 + (grp >> 1) * 16);
    // B: row = wn + nj*8 + r8, chunk = kq*2 + (grp&1)   (x2: lanes 0-15 used)
    const uint32_t bRowB = (uint32_t)((wn + r8) * 80 + (grp & 1) * 16);

    const uint4 zero4 = make_uint4(0u, 0u, 0u, 0u);

    #pragma unroll 1
    for (int kc = 0; kc < 32; kc++) {
        // issue global loads early (latency overlaps previous chunk's MMAs)
        const long ko = (long)kc * 32;
        uint4 vah = mval ? *(const uint4*)(g_Ahi + gA + ko) : zero4;
        uint4 val_ = mval ? *(const uint4*)(g_Alo + gA + ko) : zero4;
        uint4 vb0h = *(const uint4*)(g_Bhi + gB0 + ko);
        uint4 vb1h = *(const uint4*)(g_Bhi + gB1 + ko);
        uint4 vb0l = *(const uint4*)(g_Blo + gB0 + ko);
        uint4 vb1l = *(const uint4*)(g_Blo + gB1 + ko);

        __syncthreads();  // previous compute done before overwriting smem
        *(uint4*)(sm + BY_AHI + sA_st)  = vah;
        *(uint4*)(sm + BY_ALO + sA_st)  = val_;
        *(uint4*)(sm + BY_BHI + sB_st0) = vb0h;
        *(uint4*)(sm + BY_BHI + sB_st1) = vb1h;
        *(uint4*)(sm + BY_BLO + sB_st0) = vb0l;
        *(uint4*)(sm + BY_BLO + sB_st1) = vb1l;
        __syncthreads();

        #pragma unroll
        for (int kq = 0; kq < 2; kq++) {
            uint32_t ah[2][4], al[2][4];
            #pragma unroll
            for (int mi = 0; mi < 2; mi++) {
                uint32_t aoff = aRowB + mi * (16 * 80) + kq * 32;
                ldsm4(ah[mi], sbase + BY_AHI + aoff);
                ldsm4(al[mi], sbase + BY_ALO + aoff);
            }
            #pragma unroll
            for (int nj = 0; nj < 8; nj++) {
                uint32_t bh[2], bl[2];
                uint32_t boff = bRowB + nj * (8 * 80) + kq * 32;
                ldsm2(bh, sbase + BY_BHI + boff);
                ldsm2(bl, sbase + BY_BLO + boff);
                #pragma unroll
                for (int mi = 0; mi < 2; mi++) {
                    mma16816(acc[mi][nj], ah[mi], bh);
                    mma16816(acc[mi][nj], ah[mi], bl);
                    mma16816(acc[mi][nj], al[mi], bh);
                }
            }
        }
    }

    // epilogue: relu + store
    const int er = lane >> 2, ec = (lane & 3) * 2;
    #pragma unroll
    for (int mi = 0; mi < 2; mi++) {
        #pragma unroll
        for (int nj = 0; nj < 8; nj++) {
            int m = m0 + wm + mi * 16 + er;
            int n = wn + nj * 8 + ec;
            if (m < Nn) {
                float2 v;
                v.x = fmaxf(acc[mi][nj][0], 0.f);
                v.y = fmaxf(acc[mi][nj][1], 0.f);
                *(float2*)(out + (size_t)m * 256 + n) = v;
            }
            if (m + 8 < Nn) {
                float2 v;
                v.x = fmaxf(acc[mi][nj][2], 0.f);
                v.y = fmaxf(acc[mi][nj][3], 0.f);
                *(float2*)(out + (size_t)(m + 8) * 256 + n) = v;
            }
        }
    }
}

// ================= launcher =================
extern "C" void kernel_launch(void* const* d_in, const int* in_sizes, int n_in,
                              void* d_out, int out_size)
{
    const float* x    = (const float*)d_in[0];
    const int*   erow = (const int*)  d_in[1];
    const int*   ecol = (const int*)  d_in[2];
    const float* eval = (const float*)d_in[3];
    const float* W    = (const float*)d_in[4];
    const float* B    = (const float*)d_in[5];
    const float* W2   = (const float*)d_in[6];
    float* out = (float*)d_out;

    const int E = in_sizes[1] / 3;

    cudaFuncSetAttribute(gemm_final, cudaFuncAttributeMaxDynamicSharedMemorySize, SM_BYTES);

    // weight prep
    prep_wcomb<<<256, 256>>>(W2);
    prep_bcat<<<dim3(256, 4), 256>>>(W, B, W2);

    // CSR build
    zero_counts  <<<(NB + 255)/256, 256>>>();
    count_edges  <<<(3*E + 255)/256, 256>>>(erow, E);
    scan_a       <<<(NB + 1023)/1024, 1024>>>(NB);
    scan_b       <<<1, 256>>>((NB + 1023)/1024);
    scan_c       <<<(NB + 1023)/1024, 1024>>>(NB, 3*E);
    scatter_edges<<<(3*E + 255)/256, 256>>>(erow, ecol, eval, E);

    // z_r = A_r @ x for all relations (x stays L2-resident), bf16 split out
    spmm_all<<<dim3(Nn, 3), 256>>>(x);

    // x -> bf16 hi/lo (A-cat cols 768..1023)
    xconv<<<(Nn*256 + 255)/256, 256>>>(x);

    // out = relu(Acat @ Bcat) via mma.sync bf16 3-term split
    gemm_final<<<dim3(391, 1), 512, SM_BYTES>>>(out);
}